// round 9
// baseline (speedup 1.0000x reference)
#include <cuda_runtime.h>
#include <cuda_bf16.h>
#include <mma.h>
#include <math.h>
#include <stdint.h>

using namespace nvcuda;

// Problem dims (fixed by setup_inputs)
#define NN 2048   // nodes
#define BB 32     // batch
#define DD 64     // hidden dim
#define D2 128    // 2*hidden
#define EE 10     // embed dim
#define KK 3      // cheb order
#define PG (KK*DD*D2)   // 24576
#define PU (KK*D2*DD)   // 24576

// WMMA GEMM tiling: 128x256 CTA tile, 512 threads (16 warps x 32x64)
#define CTM 128
#define CTN 256
#define CTK 32
#define STAGES 3
#define A_LD 48
#define B_LD 272
#define A_TILE_B (CTM*A_LD*2)        // 12288
#define B_TILE_B (CTK*B_LD*2)        // 17408
#define STAGE_B  (2*A_TILE_B + 2*B_TILE_B)  // 59392
#define HG_SMEM  (STAGES*STAGE_B)    // 178176

// -------- device scratch (static allocation — no runtime allocs) --------
__device__ float g_Xt [NN*BB*DD];
__device__ float g_G1 [NN*BB*DD];
__device__ float g_G2 [NN*BB*DD];
__device__ float g_R  [NN*BB*DD];
__device__ float g_C  [NN*BB*D2];
__device__ float g_H1 [NN*BB*D2];
__device__ float g_H2 [NN*BB*D2];
__device__ float g_Wg [(size_t)NN*PG];
__device__ float g_Wu [(size_t)NN*PU];
__device__ float g_Bg [NN*D2];
__device__ float g_Bu [NN*DD];

// bf16 hi/lo split operands (layouts identical to their fp32 sources)
__device__ __align__(16) __nv_bfloat16 bAh [NN*NN];
__device__ __align__(16) __nv_bfloat16 bAl [NN*NN];
__device__ __align__(16) __nv_bfloat16 bXh [NN*BB*DD];
__device__ __align__(16) __nv_bfloat16 bXl [NN*BB*DD];
__device__ __align__(16) __nv_bfloat16 bG1h[NN*BB*DD];
__device__ __align__(16) __nv_bfloat16 bG1l[NN*BB*DD];
__device__ __align__(16) __nv_bfloat16 bCh [(size_t)NN*BB*D2];
__device__ __align__(16) __nv_bfloat16 bCl [(size_t)NN*BB*D2];
__device__ __align__(16) __nv_bfloat16 bH1h[(size_t)NN*BB*D2];
__device__ __align__(16) __nv_bfloat16 bH1l[(size_t)NN*BB*D2];

// =====================================================================
// helpers
// =====================================================================
__device__ __forceinline__ uint32_t smem_u32(const void* p) {
    uint32_t a;
    asm("{ .reg .u64 t; cvta.to.shared.u64 t, %1; cvt.u32.u64 %0, t; }" : "=r"(a) : "l"(p));
    return a;
}
#define CP16(dst, src) asm volatile("cp.async.cg.shared.global [%0], [%1], 16;" :: "r"(dst), "l"(src))
#define CP_COMMIT()    asm volatile("cp.async.commit_group;")
#define CP_WAIT1()     asm volatile("cp.async.wait_group 1;")
#define CP_WAIT0()     asm volatile("cp.async.wait_group 0;")

__device__ __forceinline__ void split2(float a, float b, uint32_t& hi, uint32_t& lo) {
    __nv_bfloat16 ah = __float2bfloat16(a), bh = __float2bfloat16(b);
    float ar = a - __bfloat162float(ah), br = b - __bfloat162float(bh);
    __nv_bfloat16 al = __float2bfloat16(ar), bl = __float2bfloat16(br);
    hi = (uint32_t)__bfloat16_as_ushort(ah) | ((uint32_t)__bfloat16_as_ushort(bh) << 16);
    lo = (uint32_t)__bfloat16_as_ushort(al) | ((uint32_t)__bfloat16_as_ushort(bl) << 16);
}

// =====================================================================
// adj = softmax(relu(emb @ emb^T), axis=1) -> bf16 hi/lo directly
// (g_adj fp32 eliminated; only the bf16 pair is consumed downstream)
// =====================================================================
__global__ __launch_bounds__(256) void adj_kernel(const float* __restrict__ emb) {
    __shared__ float row[NN];
    __shared__ float red[256];
    const int n = blockIdx.x;
    const int tid = threadIdx.x;
    float en[EE];
#pragma unroll
    for (int e = 0; e < EE; e++) en[e] = emb[n*EE + e];
    float lmax = 0.f;
    for (int m = tid; m < NN; m += 256) {
        float s = 0.f;
#pragma unroll
        for (int e = 0; e < EE; e++) s = fmaf(en[e], emb[m*EE + e], s);
        s = fmaxf(s, 0.f);
        row[m] = s;
        lmax = fmaxf(lmax, s);
    }
    red[tid] = lmax; __syncthreads();
    for (int s = 128; s > 0; s >>= 1) { if (tid < s) red[tid] = fmaxf(red[tid], red[tid+s]); __syncthreads(); }
    const float gmax = red[0];
    __syncthreads();
    float lsum = 0.f;
    for (int m = tid; m < NN; m += 256) { float v = __expf(row[m] - gmax); row[m] = v; lsum += v; }
    red[tid] = lsum; __syncthreads();
    for (int s = 128; s > 0; s >>= 1) { if (tid < s) red[tid] += red[tid+s]; __syncthreads(); }
    const float inv = 1.f / red[0];
    __syncthreads();
    const int m0 = tid * 8;
    uint32_t hp[4], lp[4];
#pragma unroll
    for (int p = 0; p < 4; p++)
        split2(row[m0 + 2*p] * inv, row[m0 + 2*p + 1] * inv, hp[p], lp[p]);
    *(uint4*)&bAh[(size_t)n*NN + m0] = make_uint4(hp[0], hp[1], hp[2], hp[3]);
    *(uint4*)&bAl[(size_t)n*NN + m0] = make_uint4(lp[0], lp[1], lp[2], lp[3]);
}

// =====================================================================
// Transpose x (B,N,D) -> Xt (N,B,D); also fill first half of candidate C
// =====================================================================
__global__ __launch_bounds__(256) void transpose_kernel(const float* __restrict__ x) {
    int idx = blockIdx.x * 256 + threadIdx.x;
    int d4 = idx & 15;
    int b  = (idx >> 4) & 31;
    int n  = idx >> 9;
    float4 v = *(const float4*)&x[((size_t)b*NN + n)*DD + d4*4];
    *(float4*)&g_Xt[((size_t)n*BB + b)*DD + d4*4] = v;
    *(float4*)&g_C [((size_t)n*BB + b)*D2 + d4*4] = v;
}

// =====================================================================
// Elementwise fp32 -> bf16 hi/lo split; sel: 0=Xt, 1=C
// =====================================================================
__global__ __launch_bounds__(256) void split_kernel(int sel) {
    const float* src; __nv_bfloat16 *dh, *dl;
    if (sel == 0) { src = g_Xt; dh = bXh; dl = bXl; }
    else          { src = g_C;  dh = bCh; dl = bCl; }
    size_t i = (size_t)blockIdx.x * 256 + threadIdx.x;   // float4 index
    float4 v = ((const float4*)src)[i];
    uint2 hi, lo;
    split2(v.x, v.y, hi.x, lo.x);
    split2(v.z, v.w, hi.y, lo.y);
    ((uint2*)dh)[i] = hi;
    ((uint2*)dl)[i] = lo;
}

// =====================================================================
// Per-node weight materialization — register-cached pool version.
// Output device symbol resolved in DEVICE code via selector (the host
// shadow-symbol ATS bug from R3/R4/R6 — never pass __device__ arrays
// as host-side kernel args).
// =====================================================================
__global__ __launch_bounds__(256) void wgen_kernel(int which,
                                                   const float* __restrict__ emb,
                                                   const float* __restrict__ pool) {
    float* out = (which == 0) ? g_Wg : g_Wu;
    __shared__ float es[128*EE];
    const int j4 = blockIdx.x * 256 + threadIdx.x;   // float4 index in [0, PG/4)
    const int nbase = blockIdx.y * 128;
    for (int i = threadIdx.x; i < 128*EE; i += 256)
        es[i] = emb[nbase*EE + i];
    float4 pv[EE];
#pragma unroll
    for (int e = 0; e < EE; e++) pv[e] = ((const float4*)(pool + (size_t)e*PG))[j4];
    __syncthreads();
    for (int n = 0; n < 128; n++) {
        const float* er = es + n*EE;
        float4 a = make_float4(0.f, 0.f, 0.f, 0.f);
#pragma unroll
        for (int e = 0; e < EE; e++) {
            float w = er[e];
            a.x = fmaf(w, pv[e].x, a.x); a.y = fmaf(w, pv[e].y, a.y);
            a.z = fmaf(w, pv[e].z, a.z); a.w = fmaf(w, pv[e].w, a.w);
        }
        ((float4*)(out + (size_t)(nbase + n)*PG))[j4] = a;
    }
}

__device__ __forceinline__ void bgen_body(const float* __restrict__ emb,
                                          const float* __restrict__ bpool,
                                          float* __restrict__ out, int P) {
    int idx = blockIdx.x * 256 + threadIdx.x;
    if (idx >= NN * P) return;
    int n = idx / P, p = idx - n * P;
    float acc = 0.f;
#pragma unroll
    for (int e = 0; e < EE; e++) acc = fmaf(emb[n*EE + e], bpool[e*P + p], acc);
    out[idx] = acc;
}
__global__ __launch_bounds__(256) void bgen_gate(const float* emb, const float* bp) { bgen_body(emb, bp, g_Bg, D2); }
__global__ __launch_bounds__(256) void bgen_upd (const float* emb, const float* bp) { bgen_body(emb, bp, g_Bu, DD); }

// =====================================================================
// WMMA bf16-split GEMM: Out = alpha*(A@B) + beta*Cs  [+ fused bf16 split]
// 128x256 CTA tile, 512 threads (16 warps, 32x64 each), 3-stage cp.async
// =====================================================================
__global__ __launch_bounds__(512, 1) void hgemm_kernel(int which) {
    const __nv_bfloat16 *gBh, *gBl;
    float* Out; const float* Cs; float alpha, beta; int Ncols;
    __nv_bfloat16 *Oh, *Ol;
    switch (which) {
        case 0:  gBh = bXh;  gBl = bXl;  Out = g_G1; Cs = nullptr; alpha = 1.f; beta =  0.f; Ncols = 2048; Oh = bG1h; Ol = bG1l; break;
        case 1:  gBh = bG1h; gBl = bG1l; Out = g_G2; Cs = g_Xt;    alpha = 2.f; beta = -1.f; Ncols = 2048; Oh = nullptr; Ol = nullptr; break;
        case 2:  gBh = bCh;  gBl = bCl;  Out = g_H1; Cs = nullptr; alpha = 1.f; beta =  0.f; Ncols = 4096; Oh = bH1h; Ol = bH1l; break;
        default: gBh = bH1h; gBl = bH1l; Out = g_H2; Cs = g_C;     alpha = 2.f; beta = -1.f; Ncols = 4096; Oh = nullptr; Ol = nullptr; break;
    }
    extern __shared__ __align__(16) char smem[];
    const uint32_t sb = smem_u32(smem);
    const int tid  = threadIdx.x;
    const int lane = tid & 31;
    const int wid  = tid >> 5;           // 0..15
    const int wm   = (wid & 3) * 32;     // 0,32,64,96
    const int wn   = (wid >> 2) * 64;    // 0,64,128,192
    const int mBase = blockIdx.y * CTM;
    const int nBase = blockIdx.x * CTN;

    const int aRow = tid >> 2,  aC = tid & 3;
    const int bRow = tid >> 5,  bC = tid & 31;
    auto load_stage = [&](int it, int s) {
        const int k0 = it * CTK;
        const uint32_t st = sb + s * STAGE_B;
        {
            uint32_t d = st + aRow*(A_LD*2) + aC*16;
            size_t g = (size_t)(mBase + aRow)*NN + k0 + aC*8;
            CP16(d,            bAh + g);
            CP16(d + A_TILE_B, bAl + g);
        }
#pragma unroll
        for (int i = 0; i < 2; i++) {
            int row = bRow + i*16;
            uint32_t d = st + 2*A_TILE_B + row*(B_LD*2) + bC*16;
            size_t g = (size_t)(k0 + row)*Ncols + nBase + bC*8;
            CP16(d,            gBh + g);
            CP16(d + B_TILE_B, gBl + g);
        }
        CP_COMMIT();
    };

    wmma::fragment<wmma::accumulator, 16, 16, 16, float> acc[2][4];
#pragma unroll
    for (int mi = 0; mi < 2; mi++)
#pragma unroll
        for (int ni = 0; ni < 4; ni++)
            wmma::fill_fragment(acc[mi][ni], 0.f);

    load_stage(0, 0);
    load_stage(1, 1);

    const int k_iters = NN / CTK;   // 64
    for (int it = 0; it < k_iters; it++) {
        const int s = it % STAGES;
        if (it + 1 < k_iters) { CP_WAIT1(); } else { CP_WAIT0(); }
        __syncthreads();
        if (it + 2 < k_iters) load_stage(it + 2, (it + 2) % STAGES);

        const __nv_bfloat16* Ah = (const __nv_bfloat16*)(smem + s*STAGE_B);
        const __nv_bfloat16* Al = Ah + CTM*A_LD;
        const __nv_bfloat16* Bh = (const __nv_bfloat16*)(smem + s*STAGE_B + 2*A_TILE_B);
        const __nv_bfloat16* Bl = Bh + CTK*B_LD;

#pragma unroll
        for (int kk = 0; kk < CTK; kk += 16) {
            wmma::fragment<wmma::matrix_a, 16, 16, 16, __nv_bfloat16, wmma::row_major> ah[2], al[2];
#pragma unroll
            for (int mi = 0; mi < 2; mi++) {
                wmma::load_matrix_sync(ah[mi], Ah + (wm + mi*16)*A_LD + kk, A_LD);
                wmma::load_matrix_sync(al[mi], Al + (wm + mi*16)*A_LD + kk, A_LD);
            }
#pragma unroll
            for (int ni = 0; ni < 4; ni++) {
                wmma::fragment<wmma::matrix_b, 16, 16, 16, __nv_bfloat16, wmma::row_major> bh, bl;
                wmma::load_matrix_sync(bh, Bh + kk*B_LD + wn + ni*16, B_LD);
                wmma::load_matrix_sync(bl, Bl + kk*B_LD + wn + ni*16, B_LD);
#pragma unroll
                for (int mi = 0; mi < 2; mi++) {
                    wmma::mma_sync(acc[mi][ni], ah[mi], bh, acc[mi][ni]);
                    wmma::mma_sync(acc[mi][ni], al[mi], bh, acc[mi][ni]);
                    wmma::mma_sync(acc[mi][ni], ah[mi], bl, acc[mi][ni]);
                }
            }
        }
        __syncthreads();
    }

    // ---- epilogue via smem staging (documented row-major layout) ----
    __syncthreads();
    float* stage = (float*)smem + wid * (32*64);   // 16 warps x 8KB = 128KB
#pragma unroll
    for (int mi = 0; mi < 2; mi++)
#pragma unroll
        for (int ni = 0; ni < 4; ni++) {
            if (alpha != 1.f) {
#pragma unroll
                for (int e = 0; e < acc[mi][ni].num_elements; e++)
                    acc[mi][ni].x[e] *= alpha;
            }
            wmma::store_matrix_sync(stage + mi*16*64 + ni*16, acc[mi][ni], 64, wmma::mem_row_major);
        }
    __syncwarp();

    const int col = nBase + wn + lane*2;
    for (int r = 0; r < 32; r++) {
        const int row = mBase + wm + r;
        float2 v = *(const float2*)&stage[r*64 + lane*2];
        const size_t off = (size_t)row*Ncols + col;
        if (Cs) {
            float2 cv = *(const float2*)&Cs[off];
            v.x = fmaf(beta, cv.x, v.x);
            v.y = fmaf(beta, cv.y, v.y);
        }
        *(float2*)&Out[off] = v;
        if (Oh) {
            uint32_t hi, lo;
            split2(v.x, v.y, hi, lo);
            *(uint32_t*)&Oh[off] = hi;
            *(uint32_t*)&Ol[off] = lo;
        }
    }
}

// =====================================================================
// Gate mix: zr = [Xt|G1|G2]_n (32x192) @ Wg_n (192x128) + Bg; sigmoid
// 512 threads (same math/order as proven 256-thread version)
// =====================================================================
#define JLDG 193
__global__ __launch_bounds__(512) void gate_mix_kernel() {
    extern __shared__ float sm[];
    float* Ws = sm;
    float* Av = sm + PG;
    const int n = blockIdx.x;
    const int tid = threadIdx.x;

    const float4* wsrc = (const float4*)(g_Wg + (size_t)n * PG);
    float4* wdst = (float4*)Ws;
    for (int i = tid; i < PG/4; i += 512) wdst[i] = wsrc[i];

    const float* s0 = g_Xt + (size_t)n * (BB*DD);
    const float* s1 = g_G1 + (size_t)n * (BB*DD);
    const float* s2 = g_G2 + (size_t)n * (BB*DD);
    for (int t = tid; t < BB*DD; t += 512) {
        int b = t >> 6, i = t & 63;
        Av[b*JLDG +   0 + i] = s0[t];
        Av[b*JLDG +  64 + i] = s1[t];
        Av[b*JLDG + 128 + i] = s2[t];
    }
    __syncthreads();

    const int tx = tid & 31;   // 32 o-groups of 4 -> 128 outputs
    const int ty = tid >> 5;   // 16 b-groups of 2 -> 32 batches
    float acc[2][4] = {};
#pragma unroll 4
    for (int j = 0; j < KK*DD; j++) {
        float4 wv = *(const float4*)&Ws[j*D2 + tx*4];
        float a0 = Av[(ty*2 + 0)*JLDG + j];
        float a1 = Av[(ty*2 + 1)*JLDG + j];
        acc[0][0] = fmaf(a0, wv.x, acc[0][0]); acc[0][1] = fmaf(a0, wv.y, acc[0][1]);
        acc[0][2] = fmaf(a0, wv.z, acc[0][2]); acc[0][3] = fmaf(a0, wv.w, acc[0][3]);
        acc[1][0] = fmaf(a1, wv.x, acc[1][0]); acc[1][1] = fmaf(a1, wv.y, acc[1][1]);
        acc[1][2] = fmaf(a1, wv.z, acc[1][2]); acc[1][3] = fmaf(a1, wv.w, acc[1][3]);
    }
#pragma unroll
    for (int bb = 0; bb < 2; bb++) {
        int b = ty*2 + bb;
#pragma unroll
        for (int oo = 0; oo < 4; oo++) {
            int o = tx*4 + oo;
            float v = acc[bb][oo] + g_Bg[n*D2 + o];
            float s = 1.f / (1.f + __expf(-v));
            if (o < DD)
                g_C[((size_t)n*BB + b)*D2 + DD + o] = s;
            else
                g_R[((size_t)n*BB + b)*DD + (o - DD)] = s;
        }
    }
}

// =====================================================================
// Update mix: hc = tanh([C|H1|H2]_n (32x384) @ Wu_n (384x64) + Bu)
// h = r*x + (1-r)*hc -> d_out (B,N,D). 512 threads.
// =====================================================================
#define JLDU 385
__global__ __launch_bounds__(512) void update_mix_kernel(float* __restrict__ out) {
    extern __shared__ float sm[];
    float* Ws = sm;
    float* Av = sm + PU;
    const int n = blockIdx.x;
    const int tid = threadIdx.x;

    const float4* wsrc = (const float4*)(g_Wu + (size_t)n * PU);
    float4* wdst = (float4*)Ws;
    for (int i = tid; i < PU/4; i += 512) wdst[i] = wsrc[i];

    const float* s0 = g_C  + (size_t)n * (BB*D2);
    const float* s1 = g_H1 + (size_t)n * (BB*D2);
    const float* s2 = g_H2 + (size_t)n * (BB*D2);
    for (int t = tid; t < BB*D2; t += 512) {
        int b = t >> 7, i = t & 127;
        Av[b*JLDU +   0 + i] = s0[t];
        Av[b*JLDU + 128 + i] = s1[t];
        Av[b*JLDU + 256 + i] = s2[t];
    }
    __syncthreads();

    const int tx = tid & 15;   // 16 o-groups of 4 -> 64 outputs
    const int ty = tid >> 4;   // 32 -> one batch each
    float acc[4] = {};
#pragma unroll 4
    for (int j = 0; j < KK*D2; j++) {
        float4 wv = *(const float4*)&Ws[j*DD + tx*4];
        float a0 = Av[ty*JLDU + j];
        acc[0] = fmaf(a0, wv.x, acc[0]); acc[1] = fmaf(a0, wv.y, acc[1]);
        acc[2] = fmaf(a0, wv.z, acc[2]); acc[3] = fmaf(a0, wv.w, acc[3]);
    }
    const int b = ty;
#pragma unroll
    for (int oo = 0; oo < 4; oo++) {
        int o = tx*4 + oo;
        float v  = acc[oo] + g_Bu[n*DD + o];
        float hc = tanhf(v);
        float r  = g_R [((size_t)n*BB + b)*DD + o];
        float xv = g_Xt[((size_t)n*BB + b)*DD + o];
        out[(size_t)b*(NN*DD) + (size_t)n*DD + o] = fmaf(r, xv - hc, hc);
    }
}

// =====================================================================
// Launch  (ordered so ncu -s 5 -c 1 captures hgemm_kernel(0) at launch #6)
// =====================================================================
extern "C" void kernel_launch(void* const* d_in, const int* in_sizes, int n_in,
                              void* d_out, int out_size) {
    const float* x   = (const float*)d_in[0];
    const float* emb = (const float*)d_in[2];
    const float* gwp = (const float*)d_in[3];
    const float* gbp = (const float*)d_in[4];
    const float* uwp = (const float*)d_in[5];
    const float* ubp = (const float*)d_in[6];
    float* out = (float*)d_out;

    const int GATE_SMEM = (PG + BB*JLDG) * 4;
    const int UPD_SMEM  = (PU + BB*JLDU) * 4;
    cudaFuncSetAttribute(gate_mix_kernel,   cudaFuncAttributeMaxDynamicSharedMemorySize, GATE_SMEM);
    cudaFuncSetAttribute(update_mix_kernel, cudaFuncAttributeMaxDynamicSharedMemorySize, UPD_SMEM);
    cudaFuncSetAttribute(hgemm_kernel,      cudaFuncAttributeMaxDynamicSharedMemorySize, HG_SMEM);

    const int N4_SMALL = NN*BB*DD/4;
    const int N4_BIG   = NN*BB*D2/4;

    adj_kernel<<<NN, 256>>>(emb);                               // 1: adj -> bAh/bAl (fused)
    transpose_kernel<<<(NN*BB*16)/256, 256>>>(x);               // 2
    split_kernel<<<N4_SMALL/256, 256>>>(0);                     // 3: Xt -> bXh/bXl
    wgen_kernel<<<dim3(PG/1024, NN/128), 256>>>(0, emb, gwp);   // 4
    wgen_kernel<<<dim3(PU/1024, NN/128), 256>>>(1, emb, uwp);   // 5

    hgemm_kernel<<<dim3(2048/CTN, NN/CTM), 512, HG_SMEM>>>(0);  // 6: G1 = A@X (+split)
    hgemm_kernel<<<dim3(2048/CTN, NN/CTM), 512, HG_SMEM>>>(1);  // 7: G2 = 2A@G1 - X

    bgen_gate<<<(NN*D2 + 255)/256, 256>>>(emb, gbp);            // 8
    bgen_upd <<<(NN*DD + 255)/256, 256>>>(emb, ubp);            // 9

    gate_mix_kernel<<<NN, 512, GATE_SMEM>>>();                  // 10

    split_kernel<<<N4_BIG/256, 256>>>(1);                       // 11: C -> bCh/bCl
    hgemm_kernel<<<dim3(4096/CTN, NN/CTM), 512, HG_SMEM>>>(2);  // 12: H1 = A@C (+split)
    hgemm_kernel<<<dim3(4096/CTN, NN/CTM), 512, HG_SMEM>>>(3);  // 13: H2 = 2A@H1 - C

    update_mix_kernel<<<NN, 512, UPD_SMEM>>>(out);              // 14
}

// round 11
// speedup vs baseline: 1.0419x; 1.0419x over previous
#include <cuda_runtime.h>
#include <cuda_bf16.h>
#include <mma.h>
#include <math.h>
#include <stdint.h>

using namespace nvcuda;

// Problem dims (fixed by setup_inputs)
#define NN 2048   // nodes
#define BB 32     // batch
#define DD 64     // hidden dim
#define D2 128    // 2*hidden
#define EE 10     // embed dim
#define KK 3      // cheb order
#define PG (KK*DD*D2)   // 24576
#define PU (KK*D2*DD)   // 24576

// WMMA GEMM tiling: 128x256 CTA tile, 512 threads (16 warps x 32x64)
#define CTM 128
#define CTN 256
#define CTK 32
#define STAGES 3
#define A_LD 48
#define B_LD 272
#define A_TILE_B (CTM*A_LD*2)        // 12288
#define B_TILE_B (CTK*B_LD*2)        // 17408
#define STAGE_B  (2*A_TILE_B + 2*B_TILE_B)  // 59392
#define HG_SMEM  (STAGES*STAGE_B)    // 178176

// -------- device scratch (static allocation — no runtime allocs) --------
__device__ float g_Xt [NN*BB*DD];
__device__ float g_G1 [NN*BB*DD];
__device__ float g_G2 [NN*BB*DD];
__device__ float g_R  [NN*BB*DD];
__device__ float g_C  [NN*BB*D2];
__device__ float g_H1 [NN*BB*D2];
__device__ float g_H2 [NN*BB*D2];
__device__ float g_Wg [(size_t)NN*PG];
__device__ float g_Wu [(size_t)NN*PU];
__device__ float g_Bg [NN*D2];
__device__ float g_Bu [NN*DD];

// bf16 hi/lo split operands (layouts identical to their fp32 sources)
__device__ __align__(16) __nv_bfloat16 bAh [NN*NN];
__device__ __align__(16) __nv_bfloat16 bAl [NN*NN];
__device__ __align__(16) __nv_bfloat16 bXh [NN*BB*DD];
__device__ __align__(16) __nv_bfloat16 bXl [NN*BB*DD];
__device__ __align__(16) __nv_bfloat16 bG1h[NN*BB*DD];
__device__ __align__(16) __nv_bfloat16 bG1l[NN*BB*DD];
__device__ __align__(16) __nv_bfloat16 bCh [(size_t)NN*BB*D2];
__device__ __align__(16) __nv_bfloat16 bCl [(size_t)NN*BB*D2];
__device__ __align__(16) __nv_bfloat16 bH1h[(size_t)NN*BB*D2];
__device__ __align__(16) __nv_bfloat16 bH1l[(size_t)NN*BB*D2];

// =====================================================================
// helpers
// =====================================================================
__device__ __forceinline__ uint32_t smem_u32(const void* p) {
    uint32_t a;
    asm("{ .reg .u64 t; cvta.to.shared.u64 t, %1; cvt.u32.u64 %0, t; }" : "=r"(a) : "l"(p));
    return a;
}
#define CP16(dst, src) asm volatile("cp.async.cg.shared.global [%0], [%1], 16;" :: "r"(dst), "l"(src))
#define CP_COMMIT()    asm volatile("cp.async.commit_group;")
#define CP_WAIT1()     asm volatile("cp.async.wait_group 1;")
#define CP_WAIT0()     asm volatile("cp.async.wait_group 0;")

__device__ __forceinline__ void split2(float a, float b, uint32_t& hi, uint32_t& lo) {
    __nv_bfloat16 ah = __float2bfloat16(a), bh = __float2bfloat16(b);
    float ar = a - __bfloat162float(ah), br = b - __bfloat162float(bh);
    __nv_bfloat16 al = __float2bfloat16(ar), bl = __float2bfloat16(br);
    hi = (uint32_t)__bfloat16_as_ushort(ah) | ((uint32_t)__bfloat16_as_ushort(bh) << 16);
    lo = (uint32_t)__bfloat16_as_ushort(al) | ((uint32_t)__bfloat16_as_ushort(bl) << 16);
}

// =====================================================================
// adj = softmax(relu(emb @ emb^T), axis=1) -> bf16 hi/lo directly
// =====================================================================
__global__ __launch_bounds__(256) void adj_kernel(const float* __restrict__ emb) {
    __shared__ float row[NN];
    __shared__ float red[256];
    const int n = blockIdx.x;
    const int tid = threadIdx.x;
    float en[EE];
#pragma unroll
    for (int e = 0; e < EE; e++) en[e] = emb[n*EE + e];
    float lmax = 0.f;
    for (int m = tid; m < NN; m += 256) {
        float s = 0.f;
#pragma unroll
        for (int e = 0; e < EE; e++) s = fmaf(en[e], emb[m*EE + e], s);
        s = fmaxf(s, 0.f);
        row[m] = s;
        lmax = fmaxf(lmax, s);
    }
    red[tid] = lmax; __syncthreads();
    for (int s = 128; s > 0; s >>= 1) { if (tid < s) red[tid] = fmaxf(red[tid], red[tid+s]); __syncthreads(); }
    const float gmax = red[0];
    __syncthreads();
    float lsum = 0.f;
    for (int m = tid; m < NN; m += 256) { float v = __expf(row[m] - gmax); row[m] = v; lsum += v; }
    red[tid] = lsum; __syncthreads();
    for (int s = 128; s > 0; s >>= 1) { if (tid < s) red[tid] += red[tid+s]; __syncthreads(); }
    const float inv = 1.f / red[0];
    __syncthreads();
    const int m0 = tid * 8;
    uint32_t hp[4], lp[4];
#pragma unroll
    for (int p = 0; p < 4; p++)
        split2(row[m0 + 2*p] * inv, row[m0 + 2*p + 1] * inv, hp[p], lp[p]);
    *(uint4*)&bAh[(size_t)n*NN + m0] = make_uint4(hp[0], hp[1], hp[2], hp[3]);
    *(uint4*)&bAl[(size_t)n*NN + m0] = make_uint4(lp[0], lp[1], lp[2], lp[3]);
}

// =====================================================================
// Transpose x (B,N,D) -> Xt (N,B,D); also fill first half of candidate C
// =====================================================================
__global__ __launch_bounds__(256) void transpose_kernel(const float* __restrict__ x) {
    int idx = blockIdx.x * 256 + threadIdx.x;
    int d4 = idx & 15;
    int b  = (idx >> 4) & 31;
    int n  = idx >> 9;
    float4 v = *(const float4*)&x[((size_t)b*NN + n)*DD + d4*4];
    *(float4*)&g_Xt[((size_t)n*BB + b)*DD + d4*4] = v;
    *(float4*)&g_C [((size_t)n*BB + b)*D2 + d4*4] = v;
}

// =====================================================================
// Elementwise fp32 -> bf16 hi/lo split; sel: 0=Xt, 1=C
// =====================================================================
__global__ __launch_bounds__(256) void split_kernel(int sel) {
    const float* src; __nv_bfloat16 *dh, *dl;
    if (sel == 0) { src = g_Xt; dh = bXh; dl = bXl; }
    else          { src = g_C;  dh = bCh; dl = bCl; }
    size_t i = (size_t)blockIdx.x * 256 + threadIdx.x;   // float4 index
    float4 v = ((const float4*)src)[i];
    uint2 hi, lo;
    split2(v.x, v.y, hi.x, lo.x);
    split2(v.z, v.w, hi.y, lo.y);
    ((uint2*)dh)[i] = hi;
    ((uint2*)dl)[i] = lo;
}

// =====================================================================
// Per-node weight materialization — register-cached pool version.
// Output device symbol resolved in DEVICE code via selector (host
// shadow-symbol ATS hazard).
// =====================================================================
__global__ __launch_bounds__(256) void wgen_kernel(int which,
                                                   const float* __restrict__ emb,
                                                   const float* __restrict__ pool) {
    float* out = (which == 0) ? g_Wg : g_Wu;
    __shared__ float es[128*EE];
    const int j4 = blockIdx.x * 256 + threadIdx.x;   // float4 index in [0, PG/4)
    const int nbase = blockIdx.y * 128;
    for (int i = threadIdx.x; i < 128*EE; i += 256)
        es[i] = emb[nbase*EE + i];
    float4 pv[EE];
#pragma unroll
    for (int e = 0; e < EE; e++) pv[e] = ((const float4*)(pool + (size_t)e*PG))[j4];
    __syncthreads();
    for (int n = 0; n < 128; n++) {
        const float* er = es + n*EE;
        float4 a = make_float4(0.f, 0.f, 0.f, 0.f);
#pragma unroll
        for (int e = 0; e < EE; e++) {
            float w = er[e];
            a.x = fmaf(w, pv[e].x, a.x); a.y = fmaf(w, pv[e].y, a.y);
            a.z = fmaf(w, pv[e].z, a.z); a.w = fmaf(w, pv[e].w, a.w);
        }
        ((float4*)(out + (size_t)(nbase + n)*PG))[j4] = a;
    }
}

__device__ __forceinline__ void bgen_body(const float* __restrict__ emb,
                                          const float* __restrict__ bpool,
                                          float* __restrict__ out, int P) {
    int idx = blockIdx.x * 256 + threadIdx.x;
    if (idx >= NN * P) return;
    int n = idx / P, p = idx - n * P;
    float acc = 0.f;
#pragma unroll
    for (int e = 0; e < EE; e++) acc = fmaf(emb[n*EE + e], bpool[e*P + p], acc);
    out[idx] = acc;
}
__global__ __launch_bounds__(256) void bgen_gate(const float* emb, const float* bp) { bgen_body(emb, bp, g_Bg, D2); }
__global__ __launch_bounds__(256) void bgen_upd (const float* emb, const float* bp) { bgen_body(emb, bp, g_Bu, DD); }

// =====================================================================
// WMMA bf16-split GEMM: Out = alpha*(A@B) + beta*Cs  [+ fused bf16 split]
// 128x256 CTA tile, 512 threads (16 warps, 32x64 each), 3-stage cp.async
// =====================================================================
__global__ __launch_bounds__(512, 1) void hgemm_kernel(int which) {
    const __nv_bfloat16 *gBh, *gBl;
    float* Out; const float* Cs; float alpha, beta; int Ncols;
    __nv_bfloat16 *Oh, *Ol;
    switch (which) {
        case 0:  gBh = bXh;  gBl = bXl;  Out = g_G1; Cs = nullptr; alpha = 1.f; beta =  0.f; Ncols = 2048; Oh = bG1h; Ol = bG1l; break;
        case 1:  gBh = bG1h; gBl = bG1l; Out = g_G2; Cs = g_Xt;    alpha = 2.f; beta = -1.f; Ncols = 2048; Oh = nullptr; Ol = nullptr; break;
        case 2:  gBh = bCh;  gBl = bCl;  Out = g_H1; Cs = nullptr; alpha = 1.f; beta =  0.f; Ncols = 4096; Oh = bH1h; Ol = bH1l; break;
        default: gBh = bH1h; gBl = bH1l; Out = g_H2; Cs = g_C;     alpha = 2.f; beta = -1.f; Ncols = 4096; Oh = nullptr; Ol = nullptr; break;
    }
    extern __shared__ __align__(16) char smem[];
    const uint32_t sb = smem_u32(smem);
    const int tid  = threadIdx.x;
    const int lane = tid & 31;
    const int wid  = tid >> 5;           // 0..15
    const int wm   = (wid & 3) * 32;     // 0,32,64,96
    const int wn   = (wid >> 2) * 64;    // 0,64,128,192
    const int mBase = blockIdx.y * CTM;
    const int nBase = blockIdx.x * CTN;

    const int aRow = tid >> 2,  aC = tid & 3;
    const int bRow = tid >> 5,  bC = tid & 31;
    auto load_stage = [&](int it, int s) {
        const int k0 = it * CTK;
        const uint32_t st = sb + s * STAGE_B;
        {
            uint32_t d = st + aRow*(A_LD*2) + aC*16;
            size_t g = (size_t)(mBase + aRow)*NN + k0 + aC*8;
            CP16(d,            bAh + g);
            CP16(d + A_TILE_B, bAl + g);
        }
#pragma unroll
        for (int i = 0; i < 2; i++) {
            int row = bRow + i*16;
            uint32_t d = st + 2*A_TILE_B + row*(B_LD*2) + bC*16;
            size_t g = (size_t)(k0 + row)*Ncols + nBase + bC*8;
            CP16(d,            gBh + g);
            CP16(d + B_TILE_B, gBl + g);
        }
        CP_COMMIT();
    };

    wmma::fragment<wmma::accumulator, 16, 16, 16, float> acc[2][4];
#pragma unroll
    for (int mi = 0; mi < 2; mi++)
#pragma unroll
        for (int ni = 0; ni < 4; ni++)
            wmma::fill_fragment(acc[mi][ni], 0.f);

    load_stage(0, 0);
    load_stage(1, 1);

    const int k_iters = NN / CTK;   // 64
    for (int it = 0; it < k_iters; it++) {
        const int s = it % STAGES;
        if (it + 1 < k_iters) { CP_WAIT1(); } else { CP_WAIT0(); }
        __syncthreads();
        if (it + 2 < k_iters) load_stage(it + 2, (it + 2) % STAGES);

        const __nv_bfloat16* Ah = (const __nv_bfloat16*)(smem + s*STAGE_B);
        const __nv_bfloat16* Al = Ah + CTM*A_LD;
        const __nv_bfloat16* Bh = (const __nv_bfloat16*)(smem + s*STAGE_B + 2*A_TILE_B);
        const __nv_bfloat16* Bl = Bh + CTK*B_LD;

#pragma unroll
        for (int kk = 0; kk < CTK; kk += 16) {
            wmma::fragment<wmma::matrix_a, 16, 16, 16, __nv_bfloat16, wmma::row_major> ah[2], al[2];
#pragma unroll
            for (int mi = 0; mi < 2; mi++) {
                wmma::load_matrix_sync(ah[mi], Ah + (wm + mi*16)*A_LD + kk, A_LD);
                wmma::load_matrix_sync(al[mi], Al + (wm + mi*16)*A_LD + kk, A_LD);
            }
#pragma unroll
            for (int ni = 0; ni < 4; ni++) {
                wmma::fragment<wmma::matrix_b, 16, 16, 16, __nv_bfloat16, wmma::row_major> bh, bl;
                wmma::load_matrix_sync(bh, Bh + kk*B_LD + wn + ni*16, B_LD);
                wmma::load_matrix_sync(bl, Bl + kk*B_LD + wn + ni*16, B_LD);
#pragma unroll
                for (int mi = 0; mi < 2; mi++) {
                    wmma::mma_sync(acc[mi][ni], ah[mi], bh, acc[mi][ni]);
                    wmma::mma_sync(acc[mi][ni], al[mi], bh, acc[mi][ni]);
                    wmma::mma_sync(acc[mi][ni], ah[mi], bl, acc[mi][ni]);
                }
            }
        }
        __syncthreads();
    }

    // ---- epilogue via smem staging (documented row-major layout) ----
    __syncthreads();
    float* stage = (float*)smem + wid * (32*64);   // 16 warps x 8KB = 128KB
#pragma unroll
    for (int mi = 0; mi < 2; mi++)
#pragma unroll
        for (int ni = 0; ni < 4; ni++) {
            if (alpha != 1.f) {
#pragma unroll
                for (int e = 0; e < acc[mi][ni].num_elements; e++)
                    acc[mi][ni].x[e] *= alpha;
            }
            wmma::store_matrix_sync(stage + mi*16*64 + ni*16, acc[mi][ni], 64, wmma::mem_row_major);
        }
    __syncwarp();

    const int col = nBase + wn + lane*2;
    for (int r = 0; r < 32; r++) {
        const int row = mBase + wm + r;
        float2 v = *(const float2*)&stage[r*64 + lane*2];
        const size_t off = (size_t)row*Ncols + col;
        if (Cs) {
            float2 cv = *(const float2*)&Cs[off];
            v.x = fmaf(beta, cv.x, v.x);
            v.y = fmaf(beta, cv.y, v.y);
        }
        *(float2*)&Out[off] = v;
        if (Oh) {
            uint32_t hi, lo;
            split2(v.x, v.y, hi, lo);
            *(uint32_t*)&Oh[off] = hi;
            *(uint32_t*)&Ol[off] = lo;
        }
    }
}

// =====================================================================
// Gate mix (R8-proven 256-thread): zr = [Xt|G1|G2]_n @ Wg_n + Bg; sigmoid
// =====================================================================
#define JLDG 193
__global__ __launch_bounds__(256) void gate_mix_kernel() {
    extern __shared__ float sm[];
    float* Ws = sm;
    float* Av = sm + PG;
    const int n = blockIdx.x;
    const int tid = threadIdx.x;

    const float4* wsrc = (const float4*)(g_Wg + (size_t)n * PG);
    float4* wdst = (float4*)Ws;
    for (int i = tid; i < PG/4; i += 256) wdst[i] = wsrc[i];

    const float* s0 = g_Xt + (size_t)n * (BB*DD);
    const float* s1 = g_G1 + (size_t)n * (BB*DD);
    const float* s2 = g_G2 + (size_t)n * (BB*DD);
    for (int t = tid; t < BB*DD; t += 256) {
        int b = t >> 6, i = t & 63;
        Av[b*JLDG +   0 + i] = s0[t];
        Av[b*JLDG +  64 + i] = s1[t];
        Av[b*JLDG + 128 + i] = s2[t];
    }
    __syncthreads();

    const int tx = tid & 31;
    const int ty = tid >> 5;
    float acc[4][4] = {};
#pragma unroll 4
    for (int j = 0; j < KK*DD; j++) {
        float4 wv = *(const float4*)&Ws[j*D2 + tx*4];
        float a0 = Av[(ty*4 + 0)*JLDG + j];
        float a1 = Av[(ty*4 + 1)*JLDG + j];
        float a2 = Av[(ty*4 + 2)*JLDG + j];
        float a3 = Av[(ty*4 + 3)*JLDG + j];
        acc[0][0] = fmaf(a0, wv.x, acc[0][0]); acc[0][1] = fmaf(a0, wv.y, acc[0][1]);
        acc[0][2] = fmaf(a0, wv.z, acc[0][2]); acc[0][3] = fmaf(a0, wv.w, acc[0][3]);
        acc[1][0] = fmaf(a1, wv.x, acc[1][0]); acc[1][1] = fmaf(a1, wv.y, acc[1][1]);
        acc[1][2] = fmaf(a1, wv.z, acc[1][2]); acc[1][3] = fmaf(a1, wv.w, acc[1][3]);
        acc[2][0] = fmaf(a2, wv.x, acc[2][0]); acc[2][1] = fmaf(a2, wv.y, acc[2][1]);
        acc[2][2] = fmaf(a2, wv.z, acc[2][2]); acc[2][3] = fmaf(a2, wv.w, acc[2][3]);
        acc[3][0] = fmaf(a3, wv.x, acc[3][0]); acc[3][1] = fmaf(a3, wv.y, acc[3][1]);
        acc[3][2] = fmaf(a3, wv.z, acc[3][2]); acc[3][3] = fmaf(a3, wv.w, acc[3][3]);
    }
#pragma unroll
    for (int bb = 0; bb < 4; bb++) {
        int b = ty*4 + bb;
#pragma unroll
        for (int oo = 0; oo < 4; oo++) {
            int o = tx*4 + oo;
            float v = acc[bb][oo] + g_Bg[n*D2 + o];
            float s = 1.f / (1.f + __expf(-v));
            if (o < DD)
                g_C[((size_t)n*BB + b)*D2 + DD + o] = s;
            else
                g_R[((size_t)n*BB + b)*DD + (o - DD)] = s;
        }
    }
}

// =====================================================================
// Update mix (R8-proven 256-thread): hc = tanh([C|H1|H2]_n @ Wu_n + Bu)
// h = r*x + (1-r)*hc -> d_out (B,N,D)
// =====================================================================
#define JLDU 385
__global__ __launch_bounds__(256) void update_mix_kernel(float* __restrict__ out) {
    extern __shared__ float sm[];
    float* Ws = sm;
    float* Av = sm + PU;
    const int n = blockIdx.x;
    const int tid = threadIdx.x;

    const float4* wsrc = (const float4*)(g_Wu + (size_t)n * PU);
    float4* wdst = (float4*)Ws;
    for (int i = tid; i < PU/4; i += 256) wdst[i] = wsrc[i];

    const float* s0 = g_C  + (size_t)n * (BB*D2);
    const float* s1 = g_H1 + (size_t)n * (BB*D2);
    const float* s2 = g_H2 + (size_t)n * (BB*D2);
    for (int t = tid; t < BB*D2; t += 256) {
        int b = t >> 7, i = t & 127;
        Av[b*JLDU +   0 + i] = s0[t];
        Av[b*JLDU + 128 + i] = s1[t];
        Av[b*JLDU + 256 + i] = s2[t];
    }
    __syncthreads();

    const int tx = tid & 15;
    const int ty = tid >> 4;
    float acc[2][4] = {};
#pragma unroll 4
    for (int j = 0; j < KK*D2; j++) {
        float4 wv = *(const float4*)&Ws[j*DD + tx*4];
        float a0 = Av[(ty*2 + 0)*JLDU + j];
        float a1 = Av[(ty*2 + 1)*JLDU + j];
        acc[0][0] = fmaf(a0, wv.x, acc[0][0]); acc[0][1] = fmaf(a0, wv.y, acc[0][1]);
        acc[0][2] = fmaf(a0, wv.z, acc[0][2]); acc[0][3] = fmaf(a0, wv.w, acc[0][3]);
        acc[1][0] = fmaf(a1, wv.x, acc[1][0]); acc[1][1] = fmaf(a1, wv.y, acc[1][1]);
        acc[1][2] = fmaf(a1, wv.z, acc[1][2]); acc[1][3] = fmaf(a1, wv.w, acc[1][3]);
    }
#pragma unroll
    for (int bb = 0; bb < 2; bb++) {
        int b = ty*2 + bb;
#pragma unroll
        for (int oo = 0; oo < 4; oo++) {
            int o = tx*4 + oo;
            float v  = acc[bb][oo] + g_Bu[n*DD + o];
            float hc = tanhf(v);
            float r  = g_R [((size_t)n*BB + b)*DD + o];
            float xv = g_Xt[((size_t)n*BB + b)*DD + o];
            out[(size_t)b*(NN*DD) + (size_t)n*DD + o] = fmaf(r, xv - hc, hc);
        }
    }
}

// =====================================================================
// Launch  (ordered so ncu -s 5 -c 1 captures hgemm_kernel(0) at launch #6)
// =====================================================================
extern "C" void kernel_launch(void* const* d_in, const int* in_sizes, int n_in,
                              void* d_out, int out_size) {
    const float* x   = (const float*)d_in[0];
    const float* emb = (const float*)d_in[2];
    const float* gwp = (const float*)d_in[3];
    const float* gbp = (const float*)d_in[4];
    const float* uwp = (const float*)d_in[5];
    const float* ubp = (const float*)d_in[6];
    float* out = (float*)d_out;

    const int GATE_SMEM = (PG + BB*JLDG) * 4;
    const int UPD_SMEM  = (PU + BB*JLDU) * 4;
    cudaFuncSetAttribute(gate_mix_kernel,   cudaFuncAttributeMaxDynamicSharedMemorySize, GATE_SMEM);
    cudaFuncSetAttribute(update_mix_kernel, cudaFuncAttributeMaxDynamicSharedMemorySize, UPD_SMEM);
    cudaFuncSetAttribute(hgemm_kernel,      cudaFuncAttributeMaxDynamicSharedMemorySize, HG_SMEM);

    const int N4_SMALL = NN*BB*DD/4;
    const int N4_BIG   = NN*BB*D2/4;

    adj_kernel<<<NN, 256>>>(emb);                               // 1: adj -> bAh/bAl (fused)
    transpose_kernel<<<(NN*BB*16)/256, 256>>>(x);               // 2
    split_kernel<<<N4_SMALL/256, 256>>>(0);                     // 3: Xt -> bXh/bXl
    wgen_kernel<<<dim3(PG/1024, NN/128), 256>>>(0, emb, gwp);   // 4
    wgen_kernel<<<dim3(PU/1024, NN/128), 256>>>(1, emb, uwp);   // 5

    hgemm_kernel<<<dim3(2048/CTN, NN/CTM), 512, HG_SMEM>>>(0);  // 6: G1 = A@X (+split)
    hgemm_kernel<<<dim3(2048/CTN, NN/CTM), 512, HG_SMEM>>>(1);  // 7: G2 = 2A@G1 - X

    bgen_gate<<<(NN*D2 + 255)/256, 256>>>(emb, gbp);            // 8
    bgen_upd <<<(NN*DD + 255)/256, 256>>>(emb, ubp);            // 9

    gate_mix_kernel<<<NN, 256, GATE_SMEM>>>();                  // 10

    split_kernel<<<N4_BIG/256, 256>>>(1);                       // 11: C -> bCh/bCl
    hgemm_kernel<<<dim3(4096/CTN, NN/CTM), 512, HG_SMEM>>>(2);  // 12: H1 = A@C (+split)
    hgemm_kernel<<<dim3(4096/CTN, NN/CTM), 512, HG_SMEM>>>(3);  // 13: H2 = 2A@H1 - C

    update_mix_kernel<<<NN, 256, UPD_SMEM>>>(out);              // 14
}

// round 13
// speedup vs baseline: 1.4142x; 1.3574x over previous
#include <cuda_runtime.h>
#include <cuda_bf16.h>
#include <mma.h>
#include <math.h>
#include <stdint.h>

using namespace nvcuda;

// Problem dims (fixed by setup_inputs)
#define NN 2048   // nodes
#define BB 32     // batch
#define DD 64     // hidden dim
#define D2 128    // 2*hidden
#define EE 10     // embed dim
#define KK 3      // cheb order
#define PG (KK*DD*D2)   // 24576
#define PU (KK*D2*DD)   // 24576

// All GEMMs now operate on Ncols = BB*DD = 2048 (H-phase x-half eliminated
// by the identity A@[x|z] = [G1 | A@z]).
#define NCOLS 2048

// WMMA GEMM tiling: 128x256 CTA tile, 512 threads (16 warps x 32x64)
#define CTM 128
#define CTN 256
#define CTK 32
#define STAGES 3
#define A_LD 48
#define B_LD 272
#define A_TILE_B (CTM*A_LD*2)        // 12288
#define B_TILE_B (CTK*B_LD*2)        // 17408
#define STAGE_B  (2*A_TILE_B + 2*B_TILE_B)  // 59392
#define HG_SMEM  (STAGES*STAGE_B)    // 178176

// -------- device scratch (static allocation — no runtime allocs) --------
__device__ float g_Xt  [NN*BB*DD];
__device__ float g_G1  [NN*BB*DD];
__device__ float g_G2  [NN*BB*DD];
__device__ float g_R   [NN*BB*DD];
__device__ float g_Cz  [NN*BB*DD];   // z gate (candidate second half)
__device__ float g_H1z [NN*BB*DD];   // A @ z
__device__ float g_H2z [NN*BB*DD];   // 2A@H1z - z
__device__ float g_Wg  [(size_t)NN*PG];
__device__ float g_Wu  [(size_t)NN*PU];
__device__ float g_Bg  [NN*D2];
__device__ float g_Bu  [NN*DD];

// bf16 hi/lo split operands (layouts identical to their fp32 sources)
__device__ __align__(16) __nv_bfloat16 bAh  [NN*NN];
__device__ __align__(16) __nv_bfloat16 bAl  [NN*NN];
__device__ __align__(16) __nv_bfloat16 bXh  [NN*BB*DD];
__device__ __align__(16) __nv_bfloat16 bXl  [NN*BB*DD];
__device__ __align__(16) __nv_bfloat16 bG1h [NN*BB*DD];
__device__ __align__(16) __nv_bfloat16 bG1l [NN*BB*DD];
__device__ __align__(16) __nv_bfloat16 bCzh [NN*BB*DD];
__device__ __align__(16) __nv_bfloat16 bCzl [NN*BB*DD];
__device__ __align__(16) __nv_bfloat16 bH1zh[NN*BB*DD];
__device__ __align__(16) __nv_bfloat16 bH1zl[NN*BB*DD];

// =====================================================================
// helpers
// =====================================================================
__device__ __forceinline__ uint32_t smem_u32(const void* p) {
    uint32_t a;
    asm("{ .reg .u64 t; cvta.to.shared.u64 t, %1; cvt.u32.u64 %0, t; }" : "=r"(a) : "l"(p));
    return a;
}
#define CP16(dst, src) asm volatile("cp.async.cg.shared.global [%0], [%1], 16;" :: "r"(dst), "l"(src))
#define CP_COMMIT()    asm volatile("cp.async.commit_group;")
#define CP_WAIT1()     asm volatile("cp.async.wait_group 1;")
#define CP_WAIT0()     asm volatile("cp.async.wait_group 0;")

__device__ __forceinline__ void split2(float a, float b, uint32_t& hi, uint32_t& lo) {
    __nv_bfloat16 ah = __float2bfloat16(a), bh = __float2bfloat16(b);
    float ar = a - __bfloat162float(ah), br = b - __bfloat162float(bh);
    __nv_bfloat16 al = __float2bfloat16(ar), bl = __float2bfloat16(br);
    hi = (uint32_t)__bfloat16_as_ushort(ah) | ((uint32_t)__bfloat16_as_ushort(bh) << 16);
    lo = (uint32_t)__bfloat16_as_ushort(al) | ((uint32_t)__bfloat16_as_ushort(bl) << 16);
}

// =====================================================================
// adj = softmax(relu(emb @ emb^T), axis=1) -> bf16 hi/lo directly
// =====================================================================
__global__ __launch_bounds__(256) void adj_kernel(const float* __restrict__ emb) {
    __shared__ float row[NN];
    __shared__ float red[256];
    const int n = blockIdx.x;
    const int tid = threadIdx.x;
    float en[EE];
#pragma unroll
    for (int e = 0; e < EE; e++) en[e] = emb[n*EE + e];
    float lmax = 0.f;
    for (int m = tid; m < NN; m += 256) {
        float s = 0.f;
#pragma unroll
        for (int e = 0; e < EE; e++) s = fmaf(en[e], emb[m*EE + e], s);
        s = fmaxf(s, 0.f);
        row[m] = s;
        lmax = fmaxf(lmax, s);
    }
    red[tid] = lmax; __syncthreads();
    for (int s = 128; s > 0; s >>= 1) { if (tid < s) red[tid] = fmaxf(red[tid], red[tid+s]); __syncthreads(); }
    const float gmax = red[0];
    __syncthreads();
    float lsum = 0.f;
    for (int m = tid; m < NN; m += 256) { float v = __expf(row[m] - gmax); row[m] = v; lsum += v; }
    red[tid] = lsum; __syncthreads();
    for (int s = 128; s > 0; s >>= 1) { if (tid < s) red[tid] += red[tid+s]; __syncthreads(); }
    const float inv = 1.f / red[0];
    __syncthreads();
    const int m0 = tid * 8;
    uint32_t hp[4], lp[4];
#pragma unroll
    for (int p = 0; p < 4; p++)
        split2(row[m0 + 2*p] * inv, row[m0 + 2*p + 1] * inv, hp[p], lp[p]);
    *(uint4*)&bAh[(size_t)n*NN + m0] = make_uint4(hp[0], hp[1], hp[2], hp[3]);
    *(uint4*)&bAl[(size_t)n*NN + m0] = make_uint4(lp[0], lp[1], lp[2], lp[3]);
}

// =====================================================================
// Transpose x (B,N,D) -> Xt (N,B,D)
// =====================================================================
__global__ __launch_bounds__(256) void transpose_kernel(const float* __restrict__ x) {
    int idx = blockIdx.x * 256 + threadIdx.x;
    int d4 = idx & 15;
    int b  = (idx >> 4) & 31;
    int n  = idx >> 9;
    float4 v = *(const float4*)&x[((size_t)b*NN + n)*DD + d4*4];
    *(float4*)&g_Xt[((size_t)n*BB + b)*DD + d4*4] = v;
}

// =====================================================================
// Elementwise fp32 -> bf16 hi/lo split; sel: 0=Xt, 1=Cz
// =====================================================================
__global__ __launch_bounds__(256) void split_kernel(int sel) {
    const float* src; __nv_bfloat16 *dh, *dl;
    if (sel == 0) { src = g_Xt; dh = bXh;  dl = bXl;  }
    else          { src = g_Cz; dh = bCzh; dl = bCzl; }
    size_t i = (size_t)blockIdx.x * 256 + threadIdx.x;   // float4 index
    float4 v = ((const float4*)src)[i];
    uint2 hi, lo;
    split2(v.x, v.y, hi.x, lo.x);
    split2(v.z, v.w, hi.y, lo.y);
    ((uint2*)dh)[i] = hi;
    ((uint2*)dl)[i] = lo;
}

// =====================================================================
// Per-node weight materialization — register-cached pool version.
// Output device symbol resolved in DEVICE code via selector (host
// shadow-symbol ATS hazard — never pass __device__ arrays as host args).
// =====================================================================
__global__ __launch_bounds__(256) void wgen_kernel(int which,
                                                   const float* __restrict__ emb,
                                                   const float* __restrict__ pool) {
    float* out = (which == 0) ? g_Wg : g_Wu;
    __shared__ float es[128*EE];
    const int j4 = blockIdx.x * 256 + threadIdx.x;   // float4 index in [0, PG/4)
    const int nbase = blockIdx.y * 128;
    for (int i = threadIdx.x; i < 128*EE; i += 256)
        es[i] = emb[nbase*EE + i];
    float4 pv[EE];
#pragma unroll
    for (int e = 0; e < EE; e++) pv[e] = ((const float4*)(pool + (size_t)e*PG))[j4];
    __syncthreads();
    for (int n = 0; n < 128; n++) {
        const float* er = es + n*EE;
        float4 a = make_float4(0.f, 0.f, 0.f, 0.f);
#pragma unroll
        for (int e = 0; e < EE; e++) {
            float w = er[e];
            a.x = fmaf(w, pv[e].x, a.x); a.y = fmaf(w, pv[e].y, a.y);
            a.z = fmaf(w, pv[e].z, a.z); a.w = fmaf(w, pv[e].w, a.w);
        }
        ((float4*)(out + (size_t)(nbase + n)*PG))[j4] = a;
    }
}

__device__ __forceinline__ void bgen_body(const float* __restrict__ emb,
                                          const float* __restrict__ bpool,
                                          float* __restrict__ out, int P) {
    int idx = blockIdx.x * 256 + threadIdx.x;
    if (idx >= NN * P) return;
    int n = idx / P, p = idx - n * P;
    float acc = 0.f;
#pragma unroll
    for (int e = 0; e < EE; e++) acc = fmaf(emb[n*EE + e], bpool[e*P + p], acc);
    out[idx] = acc;
}
__global__ __launch_bounds__(256) void bgen_gate(const float* emb, const float* bp) { bgen_body(emb, bp, g_Bg, D2); }
__global__ __launch_bounds__(256) void bgen_upd (const float* emb, const float* bp) { bgen_body(emb, bp, g_Bu, DD); }

// =====================================================================
// WMMA bf16-split GEMM: Out = alpha*(A@B) + beta*Cs  [+ fused bf16 split]
// All GEMMs are 2048 x 2048 x 2048 now (H-phase x-half removed by algebra).
// 128x256 CTA tile, 512 threads (16 warps, 32x64 each), 3-stage cp.async
// =====================================================================
__global__ __launch_bounds__(512, 1) void hgemm_kernel(int which) {
    const __nv_bfloat16 *gBh, *gBl;
    float* Out; const float* Cs; float alpha, beta;
    __nv_bfloat16 *Oh, *Ol;
    switch (which) {
        case 0:  gBh = bXh;   gBl = bXl;   Out = g_G1;  Cs = nullptr; alpha = 1.f; beta =  0.f; Oh = bG1h;  Ol = bG1l;  break;
        case 1:  gBh = bG1h;  gBl = bG1l;  Out = g_G2;  Cs = g_Xt;    alpha = 2.f; beta = -1.f; Oh = nullptr; Ol = nullptr; break;
        case 2:  gBh = bCzh;  gBl = bCzl;  Out = g_H1z; Cs = nullptr; alpha = 1.f; beta =  0.f; Oh = bH1zh; Ol = bH1zl; break;
        default: gBh = bH1zh; gBl = bH1zl; Out = g_H2z; Cs = g_Cz;    alpha = 2.f; beta = -1.f; Oh = nullptr; Ol = nullptr; break;
    }
    extern __shared__ __align__(16) char smem[];
    const uint32_t sb = smem_u32(smem);
    const int tid  = threadIdx.x;
    const int lane = tid & 31;
    const int wid  = tid >> 5;           // 0..15
    const int wm   = (wid & 3) * 32;     // 0,32,64,96
    const int wn   = (wid >> 2) * 64;    // 0,64,128,192
    const int mBase = blockIdx.y * CTM;
    const int nBase = blockIdx.x * CTN;

    const int aRow = tid >> 2,  aC = tid & 3;
    const int bRow = tid >> 5,  bC = tid & 31;
    auto load_stage = [&](int it, int s) {
        const int k0 = it * CTK;
        const uint32_t st = sb + s * STAGE_B;
        {
            uint32_t d = st + aRow*(A_LD*2) + aC*16;
            size_t g = (size_t)(mBase + aRow)*NN + k0 + aC*8;
            CP16(d,            bAh + g);
            CP16(d + A_TILE_B, bAl + g);
        }
#pragma unroll
        for (int i = 0; i < 2; i++) {
            int row = bRow + i*16;
            uint32_t d = st + 2*A_TILE_B + row*(B_LD*2) + bC*16;
            size_t g = (size_t)(k0 + row)*NCOLS + nBase + bC*8;
            CP16(d,            gBh + g);
            CP16(d + B_TILE_B, gBl + g);
        }
        CP_COMMIT();
    };

    wmma::fragment<wmma::accumulator, 16, 16, 16, float> acc[2][4];
#pragma unroll
    for (int mi = 0; mi < 2; mi++)
#pragma unroll
        for (int ni = 0; ni < 4; ni++)
            wmma::fill_fragment(acc[mi][ni], 0.f);

    load_stage(0, 0);
    load_stage(1, 1);

    const int k_iters = NN / CTK;   // 64
    for (int it = 0; it < k_iters; it++) {
        const int s = it % STAGES;
        if (it + 1 < k_iters) { CP_WAIT1(); } else { CP_WAIT0(); }
        __syncthreads();
        if (it + 2 < k_iters) load_stage(it + 2, (it + 2) % STAGES);

        const __nv_bfloat16* Ah = (const __nv_bfloat16*)(smem + s*STAGE_B);
        const __nv_bfloat16* Al = Ah + CTM*A_LD;
        const __nv_bfloat16* Bh = (const __nv_bfloat16*)(smem + s*STAGE_B + 2*A_TILE_B);
        const __nv_bfloat16* Bl = Bh + CTK*B_LD;

#pragma unroll
        for (int kk = 0; kk < CTK; kk += 16) {
            wmma::fragment<wmma::matrix_a, 16, 16, 16, __nv_bfloat16, wmma::row_major> ah[2], al[2];
#pragma unroll
            for (int mi = 0; mi < 2; mi++) {
                wmma::load_matrix_sync(ah[mi], Ah + (wm + mi*16)*A_LD + kk, A_LD);
                wmma::load_matrix_sync(al[mi], Al + (wm + mi*16)*A_LD + kk, A_LD);
            }
#pragma unroll
            for (int ni = 0; ni < 4; ni++) {
                wmma::fragment<wmma::matrix_b, 16, 16, 16, __nv_bfloat16, wmma::row_major> bh, bl;
                wmma::load_matrix_sync(bh, Bh + kk*B_LD + wn + ni*16, B_LD);
                wmma::load_matrix_sync(bl, Bl + kk*B_LD + wn + ni*16, B_LD);
#pragma unroll
                for (int mi = 0; mi < 2; mi++) {
                    wmma::mma_sync(acc[mi][ni], ah[mi], bh, acc[mi][ni]);
                    wmma::mma_sync(acc[mi][ni], al[mi], bh, acc[mi][ni]);
                    wmma::mma_sync(acc[mi][ni], ah[mi], bl, acc[mi][ni]);
                }
            }
        }
        __syncthreads();
    }

    // ---- epilogue via smem staging (documented row-major layout) ----
    __syncthreads();
    float* stage = (float*)smem + wid * (32*64);   // 16 warps x 8KB = 128KB
#pragma unroll
    for (int mi = 0; mi < 2; mi++)
#pragma unroll
        for (int ni = 0; ni < 4; ni++) {
            if (alpha != 1.f) {
#pragma unroll
                for (int e = 0; e < acc[mi][ni].num_elements; e++)
                    acc[mi][ni].x[e] *= alpha;
            }
            wmma::store_matrix_sync(stage + mi*16*64 + ni*16, acc[mi][ni], 64, wmma::mem_row_major);
        }
    __syncwarp();

    const int col = nBase + wn + lane*2;
    for (int r = 0; r < 32; r++) {
        const int row = mBase + wm + r;
        float2 v = *(const float2*)&stage[r*64 + lane*2];
        const size_t off = (size_t)row*NCOLS + col;
        if (Cs) {
            float2 cv = *(const float2*)&Cs[off];
            v.x = fmaf(beta, cv.x, v.x);
            v.y = fmaf(beta, cv.y, v.y);
        }
        *(float2*)&Out[off] = v;
        if (Oh) {
            uint32_t hi, lo;
            split2(v.x, v.y, hi, lo);
            *(uint32_t*)&Oh[off] = hi;
            *(uint32_t*)&Ol[off] = lo;
        }
    }
}

// =====================================================================
// Gate mix (proven 256-thread): zr = [Xt|G1|G2]_n @ Wg_n + Bg; sigmoid
// z -> g_Cz, r -> g_R
// =====================================================================
#define JLDG 193
__global__ __launch_bounds__(256) void gate_mix_kernel() {
    extern __shared__ float sm[];
    float* Ws = sm;
    float* Av = sm + PG;
    const int n = blockIdx.x;
    const int tid = threadIdx.x;

    const float4* wsrc = (const float4*)(g_Wg + (size_t)n * PG);
    float4* wdst = (float4*)Ws;
    for (int i = tid; i < PG/4; i += 256) wdst[i] = wsrc[i];

    const float* s0 = g_Xt + (size_t)n * (BB*DD);
    const float* s1 = g_G1 + (size_t)n * (BB*DD);
    const float* s2 = g_G2 + (size_t)n * (BB*DD);
    for (int t = tid; t < BB*DD; t += 256) {
        int b = t >> 6, i = t & 63;
        Av[b*JLDG +   0 + i] = s0[t];
        Av[b*JLDG +  64 + i] = s1[t];
        Av[b*JLDG + 128 + i] = s2[t];
    }
    __syncthreads();

    const int tx = tid & 31;
    const int ty = tid >> 5;
    float acc[4][4] = {};
#pragma unroll 4
    for (int j = 0; j < KK*DD; j++) {
        float4 wv = *(const float4*)&Ws[j*D2 + tx*4];
        float a0 = Av[(ty*4 + 0)*JLDG + j];
        float a1 = Av[(ty*4 + 1)*JLDG + j];
        float a2 = Av[(ty*4 + 2)*JLDG + j];
        float a3 = Av[(ty*4 + 3)*JLDG + j];
        acc[0][0] = fmaf(a0, wv.x, acc[0][0]); acc[0][1] = fmaf(a0, wv.y, acc[0][1]);
        acc[0][2] = fmaf(a0, wv.z, acc[0][2]); acc[0][3] = fmaf(a0, wv.w, acc[0][3]);
        acc[1][0] = fmaf(a1, wv.x, acc[1][0]); acc[1][1] = fmaf(a1, wv.y, acc[1][1]);
        acc[1][2] = fmaf(a1, wv.z, acc[1][2]); acc[1][3] = fmaf(a1, wv.w, acc[1][3]);
        acc[2][0] = fmaf(a2, wv.x, acc[2][0]); acc[2][1] = fmaf(a2, wv.y, acc[2][1]);
        acc[2][2] = fmaf(a2, wv.z, acc[2][2]); acc[2][3] = fmaf(a2, wv.w, acc[2][3]);
        acc[3][0] = fmaf(a3, wv.x, acc[3][0]); acc[3][1] = fmaf(a3, wv.y, acc[3][1]);
        acc[3][2] = fmaf(a3, wv.z, acc[3][2]); acc[3][3] = fmaf(a3, wv.w, acc[3][3]);
    }
#pragma unroll
    for (int bb = 0; bb < 4; bb++) {
        int b = ty*4 + bb;
#pragma unroll
        for (int oo = 0; oo < 4; oo++) {
            int o = tx*4 + oo;
            float v = acc[bb][oo] + g_Bg[n*D2 + o];
            float s = 1.f / (1.f + __expf(-v));
            if (o < DD)
                g_Cz[((size_t)n*BB + b)*DD + o] = s;          // z
            else
                g_R[((size_t)n*BB + b)*DD + (o - DD)] = s;    // r
        }
    }
}

// =====================================================================
// Update mix: hc = tanh([x|z|G1|H1z|G2|H2z]_n (32x384) @ Wu_n (384x64) + Bu)
// (row order matches Wu: k=0 -> candidate [x|z], k=1 -> A@cand [G1|H1z],
//  k=2 -> cheb2 [G2|H2z])
// h = r*x + (1-r)*hc -> d_out (B,N,D)
// =====================================================================
#define JLDU 385
__global__ __launch_bounds__(256) void update_mix_kernel(float* __restrict__ out) {
    extern __shared__ float sm[];
    float* Ws = sm;
    float* Av = sm + PU;
    const int n = blockIdx.x;
    const int tid = threadIdx.x;

    const float4* wsrc = (const float4*)(g_Wu + (size_t)n * PU);
    float4* wdst = (float4*)Ws;
    for (int i = tid; i < PU/4; i += 256) wdst[i] = wsrc[i];

    const size_t base = (size_t)n * (BB*DD);
    const float* s0 = g_Xt  + base;
    const float* s1 = g_Cz  + base;
    const float* s2 = g_G1  + base;
    const float* s3 = g_H1z + base;
    const float* s4 = g_G2  + base;
    const float* s5 = g_H2z + base;
    for (int t = tid; t < BB*DD; t += 256) {
        int b = t >> 6, i = t & 63;
        float* av = Av + b*JLDU + i;
        av[  0] = s0[t];
        av[ 64] = s1[t];
        av[128] = s2[t];
        av[192] = s3[t];
        av[256] = s4[t];
        av[320] = s5[t];
    }
    __syncthreads();

    const int tx = tid & 15;
    const int ty = tid >> 4;
    float acc[2][4] = {};
#pragma unroll 4
    for (int j = 0; j < KK*D2; j++) {
        float4 wv = *(const float4*)&Ws[j*DD + tx*4];
        float a0 = Av[(ty*2 + 0)*JLDU + j];
        float a1 = Av[(ty*2 + 1)*JLDU + j];
        acc[0][0] = fmaf(a0, wv.x, acc[0][0]); acc[0][1] = fmaf(a0, wv.y, acc[0][1]);
        acc[0][2] = fmaf(a0, wv.z, acc[0][2]); acc[0][3] = fmaf(a0, wv.w, acc[0][3]);
        acc[1][0] = fmaf(a1, wv.x, acc[1][0]); acc[1][1] = fmaf(a1, wv.y, acc[1][1]);
        acc[1][2] = fmaf(a1, wv.z, acc[1][2]); acc[1][3] = fmaf(a1, wv.w, acc[1][3]);
    }
#pragma unroll
    for (int bb = 0; bb < 2; bb++) {
        int b = ty*2 + bb;
#pragma unroll
        for (int oo = 0; oo < 4; oo++) {
            int o = tx*4 + oo;
            float v  = acc[bb][oo] + g_Bu[n*DD + o];
            float hc = tanhf(v);
            float r  = g_R [((size_t)n*BB + b)*DD + o];
            float xv = g_Xt[((size_t)n*BB + b)*DD + o];
            out[(size_t)b*(NN*DD) + (size_t)n*DD + o] = fmaf(r, xv - hc, hc);
        }
    }
}

// =====================================================================
// Launch
// =====================================================================
extern "C" void kernel_launch(void* const* d_in, const int* in_sizes, int n_in,
                              void* d_out, int out_size) {
    const float* x   = (const float*)d_in[0];
    const float* emb = (const float*)d_in[2];
    const float* gwp = (const float*)d_in[3];
    const float* gbp = (const float*)d_in[4];
    const float* uwp = (const float*)d_in[5];
    const float* ubp = (const float*)d_in[6];
    float* out = (float*)d_out;

    const int GATE_SMEM = (PG + BB*JLDG) * 4;
    const int UPD_SMEM  = (PU + BB*JLDU) * 4;
    cudaFuncSetAttribute(gate_mix_kernel,   cudaFuncAttributeMaxDynamicSharedMemorySize, GATE_SMEM);
    cudaFuncSetAttribute(update_mix_kernel, cudaFuncAttributeMaxDynamicSharedMemorySize, UPD_SMEM);
    cudaFuncSetAttribute(hgemm_kernel,      cudaFuncAttributeMaxDynamicSharedMemorySize, HG_SMEM);

    const int N4 = NN*BB*DD/4;
    const dim3 GEMM_GRID(NCOLS/CTN, NN/CTM);   // (8, 16) = 128 CTAs — 1 wave

    adj_kernel<<<NN, 256>>>(emb);                            // adj -> bAh/bAl (fused)
    transpose_kernel<<<(NN*BB*16)/256, 256>>>(x);
    split_kernel<<<N4/256, 256>>>(0);                        // Xt -> bXh/bXl
    wgen_kernel<<<dim3(PG/1024, NN/128), 256>>>(0, emb, gwp);
    wgen_kernel<<<dim3(PU/1024, NN/128), 256>>>(1, emb, uwp);

    hgemm_kernel<<<GEMM_GRID, 512, HG_SMEM>>>(0);            // G1 = A@x (+split)
    hgemm_kernel<<<GEMM_GRID, 512, HG_SMEM>>>(1);            // G2 = 2A@G1 - x

    bgen_gate<<<(NN*D2 + 255)/256, 256>>>(emb, gbp);
    bgen_upd <<<(NN*DD + 255)/256, 256>>>(emb, ubp);

    gate_mix_kernel<<<NN, 256, GATE_SMEM>>>();               // z -> g_Cz, r -> g_R

    split_kernel<<<N4/256, 256>>>(1);                        // Cz -> bCzh/bCzl
    hgemm_kernel<<<GEMM_GRID, 512, HG_SMEM>>>(2);            // H1z = A@z (+split)
    hgemm_kernel<<<GEMM_GRID, 512, HG_SMEM>>>(3);            // H2z = 2A@H1z - z

    update_mix_kernel<<<NN, 256, UPD_SMEM>>>(out);
}

// round 15
// speedup vs baseline: 1.4354x; 1.0149x over previous
#include <cuda_runtime.h>
#include <cuda_bf16.h>
#include <mma.h>
#include <math.h>
#include <stdint.h>

using namespace nvcuda;

// Problem dims (fixed by setup_inputs)
#define NN 2048   // nodes
#define BB 32     // batch
#define DD 64     // hidden dim
#define D2 128    // 2*hidden
#define EE 10     // embed dim
#define KK 3      // cheb order
#define PG (KK*DD*D2)   // 24576
#define PU (KK*D2*DD)   // 24576

// All GEMMs operate on Ncols = BB*DD = 2048 (H-phase x-half eliminated
// by the identity A@[x|z] = [G1 | A@z]).
#define NCOLS 2048

// WMMA GEMM tiling: 128x128 CTA tile, 256 threads (8 warps x 32x64),
// 3-stage cp.async, sized for 2 CTAs/SM (fills sync/load bubbles).
#define CTM 128
#define CTN 128
#define CTK 32
#define STAGES 3
#define A_LD 40                      // 80 B/row  (16B multiple — wmma-legal)
#define B_LD 136                     // 272 B/row (16B multiple)
#define A_TILE_B (CTM*A_LD*2)        // 10240
#define B_TILE_B (CTK*B_LD*2)        // 8704
#define STAGE_B  (2*A_TILE_B + 2*B_TILE_B)  // 37888
#define HG_SMEM  (STAGES*STAGE_B)    // 113664  (2 per SM: 227328 <= 232448)

// -------- device scratch (static allocation — no runtime allocs) --------
__device__ float g_Xt  [NN*BB*DD];
__device__ float g_G1  [NN*BB*DD];
__device__ float g_G2  [NN*BB*DD];
__device__ float g_R   [NN*BB*DD];
__device__ float g_Cz  [NN*BB*DD];   // z gate (candidate second half)
__device__ float g_H1z [NN*BB*DD];   // A @ z
__device__ float g_H2z [NN*BB*DD];   // 2A@H1z - z
__device__ float g_Wg  [(size_t)NN*PG];
__device__ float g_Wu  [(size_t)NN*PU];
__device__ float g_Bg  [NN*D2];
__device__ float g_Bu  [NN*DD];

// bf16 hi/lo split operands (layouts identical to their fp32 sources)
__device__ __align__(16) __nv_bfloat16 bAh  [NN*NN];
__device__ __align__(16) __nv_bfloat16 bAl  [NN*NN];
__device__ __align__(16) __nv_bfloat16 bXh  [NN*BB*DD];
__device__ __align__(16) __nv_bfloat16 bXl  [NN*BB*DD];
__device__ __align__(16) __nv_bfloat16 bG1h [NN*BB*DD];
__device__ __align__(16) __nv_bfloat16 bG1l [NN*BB*DD];
__device__ __align__(16) __nv_bfloat16 bCzh [NN*BB*DD];
__device__ __align__(16) __nv_bfloat16 bCzl [NN*BB*DD];
__device__ __align__(16) __nv_bfloat16 bH1zh[NN*BB*DD];
__device__ __align__(16) __nv_bfloat16 bH1zl[NN*BB*DD];

// =====================================================================
// helpers
// =====================================================================
__device__ __forceinline__ uint32_t smem_u32(const void* p) {
    uint32_t a;
    asm("{ .reg .u64 t; cvta.to.shared.u64 t, %1; cvt.u32.u64 %0, t; }" : "=r"(a) : "l"(p));
    return a;
}
#define CP16(dst, src) asm volatile("cp.async.cg.shared.global [%0], [%1], 16;" :: "r"(dst), "l"(src))
#define CP_COMMIT()    asm volatile("cp.async.commit_group;")
#define CP_WAIT1()     asm volatile("cp.async.wait_group 1;")
#define CP_WAIT0()     asm volatile("cp.async.wait_group 0;")

__device__ __forceinline__ void split2(float a, float b, uint32_t& hi, uint32_t& lo) {
    __nv_bfloat16 ah = __float2bfloat16(a), bh = __float2bfloat16(b);
    float ar = a - __bfloat162float(ah), br = b - __bfloat162float(bh);
    __nv_bfloat16 al = __float2bfloat16(ar), bl = __float2bfloat16(br);
    hi = (uint32_t)__bfloat16_as_ushort(ah) | ((uint32_t)__bfloat16_as_ushort(bh) << 16);
    lo = (uint32_t)__bfloat16_as_ushort(al) | ((uint32_t)__bfloat16_as_ushort(bl) << 16);
}

// =====================================================================
// adj = softmax(relu(emb @ emb^T), axis=1) -> bf16 hi/lo directly
// =====================================================================
__global__ __launch_bounds__(256) void adj_kernel(const float* __restrict__ emb) {
    __shared__ float row[NN];
    __shared__ float red[256];
    const int n = blockIdx.x;
    const int tid = threadIdx.x;
    float en[EE];
#pragma unroll
    for (int e = 0; e < EE; e++) en[e] = emb[n*EE + e];
    float lmax = 0.f;
    for (int m = tid; m < NN; m += 256) {
        float s = 0.f;
#pragma unroll
        for (int e = 0; e < EE; e++) s = fmaf(en[e], emb[m*EE + e], s);
        s = fmaxf(s, 0.f);
        row[m] = s;
        lmax = fmaxf(lmax, s);
    }
    red[tid] = lmax; __syncthreads();
    for (int s = 128; s > 0; s >>= 1) { if (tid < s) red[tid] = fmaxf(red[tid], red[tid+s]); __syncthreads(); }
    const float gmax = red[0];
    __syncthreads();
    float lsum = 0.f;
    for (int m = tid; m < NN; m += 256) { float v = __expf(row[m] - gmax); row[m] = v; lsum += v; }
    red[tid] = lsum; __syncthreads();
    for (int s = 128; s > 0; s >>= 1) { if (tid < s) red[tid] += red[tid+s]; __syncthreads(); }
    const float inv = 1.f / red[0];
    __syncthreads();
    const int m0 = tid * 8;
    uint32_t hp[4], lp[4];
#pragma unroll
    for (int p = 0; p < 4; p++)
        split2(row[m0 + 2*p] * inv, row[m0 + 2*p + 1] * inv, hp[p], lp[p]);
    *(uint4*)&bAh[(size_t)n*NN + m0] = make_uint4(hp[0], hp[1], hp[2], hp[3]);
    *(uint4*)&bAl[(size_t)n*NN + m0] = make_uint4(lp[0], lp[1], lp[2], lp[3]);
}

// =====================================================================
// Transpose x (B,N,D) -> Xt (N,B,D) fp32 + fused bf16 hi/lo split
// =====================================================================
__global__ __launch_bounds__(256) void transpose_kernel(const float* __restrict__ x) {
    int idx = blockIdx.x * 256 + threadIdx.x;
    int d4 = idx & 15;
    int b  = (idx >> 4) & 31;
    int n  = idx >> 9;
    float4 v = *(const float4*)&x[((size_t)b*NN + n)*DD + d4*4];
    size_t off = ((size_t)n*BB + b)*DD + d4*4;
    *(float4*)&g_Xt[off] = v;
    uint2 hi, lo;
    split2(v.x, v.y, hi.x, lo.x);
    split2(v.z, v.w, hi.y, lo.y);
    *(uint2*)&bXh[off] = hi;
    *(uint2*)&bXl[off] = lo;
}

// =====================================================================
// Per-node weight materialization — register-cached pool version.
// Output device symbol resolved in DEVICE code via selector (host
// shadow-symbol ATS hazard — never pass __device__ arrays as host args).
// =====================================================================
__global__ __launch_bounds__(256) void wgen_kernel(int which,
                                                   const float* __restrict__ emb,
                                                   const float* __restrict__ pool) {
    float* out = (which == 0) ? g_Wg : g_Wu;
    __shared__ float es[128*EE];
    const int j4 = blockIdx.x * 256 + threadIdx.x;   // float4 index in [0, PG/4)
    const int nbase = blockIdx.y * 128;
    for (int i = threadIdx.x; i < 128*EE; i += 256)
        es[i] = emb[nbase*EE + i];
    float4 pv[EE];
#pragma unroll
    for (int e = 0; e < EE; e++) pv[e] = ((const float4*)(pool + (size_t)e*PG))[j4];
    __syncthreads();
    for (int n = 0; n < 128; n++) {
        const float* er = es + n*EE;
        float4 a = make_float4(0.f, 0.f, 0.f, 0.f);
#pragma unroll
        for (int e = 0; e < EE; e++) {
            float w = er[e];
            a.x = fmaf(w, pv[e].x, a.x); a.y = fmaf(w, pv[e].y, a.y);
            a.z = fmaf(w, pv[e].z, a.z); a.w = fmaf(w, pv[e].w, a.w);
        }
        ((float4*)(out + (size_t)(nbase + n)*PG))[j4] = a;
    }
}

__device__ __forceinline__ void bgen_body(const float* __restrict__ emb,
                                          const float* __restrict__ bpool,
                                          float* __restrict__ out, int P) {
    int idx = blockIdx.x * 256 + threadIdx.x;
    if (idx >= NN * P) return;
    int n = idx / P, p = idx - n * P;
    float acc = 0.f;
#pragma unroll
    for (int e = 0; e < EE; e++) acc = fmaf(emb[n*EE + e], bpool[e*P + p], acc);
    out[idx] = acc;
}
__global__ __launch_bounds__(256) void bgen_gate(const float* emb, const float* bp) { bgen_body(emb, bp, g_Bg, D2); }
__global__ __launch_bounds__(256) void bgen_upd (const float* emb, const float* bp) { bgen_body(emb, bp, g_Bu, DD); }

// =====================================================================
// WMMA bf16-split GEMM: Out = alpha*(A@B) + beta*Cs  [+ fused bf16 split]
// All GEMMs 2048^3. 128x128 tile, 256 threads, 3-stage cp.async,
// 2 CTAs/SM (grid 256 = single wave at occ 2).
// =====================================================================
__global__ __launch_bounds__(256, 2) void hgemm_kernel(int which) {
    const __nv_bfloat16 *gBh, *gBl;
    float* Out; const float* Cs; float alpha, beta;
    __nv_bfloat16 *Oh, *Ol;
    switch (which) {
        case 0:  gBh = bXh;   gBl = bXl;   Out = g_G1;  Cs = nullptr; alpha = 1.f; beta =  0.f; Oh = bG1h;  Ol = bG1l;  break;
        case 1:  gBh = bG1h;  gBl = bG1l;  Out = g_G2;  Cs = g_Xt;    alpha = 2.f; beta = -1.f; Oh = nullptr; Ol = nullptr; break;
        case 2:  gBh = bCzh;  gBl = bCzl;  Out = g_H1z; Cs = nullptr; alpha = 1.f; beta =  0.f; Oh = bH1zh; Ol = bH1zl; break;
        default: gBh = bH1zh; gBl = bH1zl; Out = g_H2z; Cs = g_Cz;    alpha = 2.f; beta = -1.f; Oh = nullptr; Ol = nullptr; break;
    }
    extern __shared__ __align__(16) char smem[];
    const uint32_t sb = smem_u32(smem);
    const int tid  = threadIdx.x;
    const int lane = tid & 31;
    const int wid  = tid >> 5;           // 0..7
    const int wm   = (wid & 3) * 32;     // 0,32,64,96
    const int wn   = (wid >> 2) * 64;    // 0,64
    const int mBase = blockIdx.y * CTM;
    const int nBase = blockIdx.x * CTN;

    // A tile: 128 rows x 32 bf16 (64 B/row = 4 cp16): 2 iters over rows.
    const int aRow = tid >> 2,  aC = tid & 3;
    // B tile: 32 rows x 128 bf16 (256 B/row = 16 cp16): 2 iters over rows.
    const int bRow = tid >> 4,  bC = tid & 15;
    auto load_stage = [&](int it, int s) {
        const int k0 = it * CTK;
        const uint32_t st = sb + s * STAGE_B;
#pragma unroll
        for (int i = 0; i < 2; i++) {
            int row = aRow + i*64;
            uint32_t d = st + row*(A_LD*2) + aC*16;
            size_t g = (size_t)(mBase + row)*NN + k0 + aC*8;
            CP16(d,            bAh + g);
            CP16(d + A_TILE_B, bAl + g);
        }
#pragma unroll
        for (int i = 0; i < 2; i++) {
            int row = bRow + i*16;
            uint32_t d = st + 2*A_TILE_B + row*(B_LD*2) + bC*16;
            size_t g = (size_t)(k0 + row)*NCOLS + nBase + bC*8;
            CP16(d,            gBh + g);
            CP16(d + B_TILE_B, gBl + g);
        }
        CP_COMMIT();
    };

    wmma::fragment<wmma::accumulator, 16, 16, 16, float> acc[2][4];
#pragma unroll
    for (int mi = 0; mi < 2; mi++)
#pragma unroll
        for (int ni = 0; ni < 4; ni++)
            wmma::fill_fragment(acc[mi][ni], 0.f);

    load_stage(0, 0);
    load_stage(1, 1);

    const int k_iters = NN / CTK;   // 64
    for (int it = 0; it < k_iters; it++) {
        const int s = it % STAGES;
        if (it + 1 < k_iters) { CP_WAIT1(); } else { CP_WAIT0(); }
        __syncthreads();
        if (it + 2 < k_iters) load_stage(it + 2, (it + 2) % STAGES);

        const __nv_bfloat16* Ah = (const __nv_bfloat16*)(smem + s*STAGE_B);
        const __nv_bfloat16* Al = Ah + CTM*A_LD;
        const __nv_bfloat16* Bh = (const __nv_bfloat16*)(smem + s*STAGE_B + 2*A_TILE_B);
        const __nv_bfloat16* Bl = Bh + CTK*B_LD;

#pragma unroll
        for (int kk = 0; kk < CTK; kk += 16) {
            wmma::fragment<wmma::matrix_a, 16, 16, 16, __nv_bfloat16, wmma::row_major> ah[2], al[2];
#pragma unroll
            for (int mi = 0; mi < 2; mi++) {
                wmma::load_matrix_sync(ah[mi], Ah + (wm + mi*16)*A_LD + kk, A_LD);
                wmma::load_matrix_sync(al[mi], Al + (wm + mi*16)*A_LD + kk, A_LD);
            }
#pragma unroll
            for (int ni = 0; ni < 4; ni++) {
                wmma::fragment<wmma::matrix_b, 16, 16, 16, __nv_bfloat16, wmma::row_major> bh, bl;
                wmma::load_matrix_sync(bh, Bh + kk*B_LD + wn + ni*16, B_LD);
                wmma::load_matrix_sync(bl, Bl + kk*B_LD + wn + ni*16, B_LD);
#pragma unroll
                for (int mi = 0; mi < 2; mi++) {
                    wmma::mma_sync(acc[mi][ni], ah[mi], bh, acc[mi][ni]);
                    wmma::mma_sync(acc[mi][ni], al[mi], bh, acc[mi][ni]);
                    wmma::mma_sync(acc[mi][ni], ah[mi], bl, acc[mi][ni]);
                }
            }
        }
        __syncthreads();
    }

    // ---- epilogue via smem staging (documented row-major layout) ----
    __syncthreads();
    float* stage = (float*)smem + wid * (32*64);   // 8 warps x 8KB = 64KB
#pragma unroll
    for (int mi = 0; mi < 2; mi++)
#pragma unroll
        for (int ni = 0; ni < 4; ni++) {
            if (alpha != 1.f) {
#pragma unroll
                for (int e = 0; e < acc[mi][ni].num_elements; e++)
                    acc[mi][ni].x[e] *= alpha;
            }
            wmma::store_matrix_sync(stage + mi*16*64 + ni*16, acc[mi][ni], 64, wmma::mem_row_major);
        }
    __syncwarp();

    const int col = nBase + wn + lane*2;
    for (int r = 0; r < 32; r++) {
        const int row = mBase + wm + r;
        float2 v = *(const float2*)&stage[r*64 + lane*2];
        const size_t off = (size_t)row*NCOLS + col;
        if (Cs) {
            float2 cv = *(const float2*)&Cs[off];
            v.x = fmaf(beta, cv.x, v.x);
            v.y = fmaf(beta, cv.y, v.y);
        }
        *(float2*)&Out[off] = v;
        if (Oh) {
            uint32_t hi, lo;
            split2(v.x, v.y, hi, lo);
            *(uint32_t*)&Oh[off] = hi;
            *(uint32_t*)&Ol[off] = lo;
        }
    }
}

// =====================================================================
// Gate mix (proven 256-thread): zr = [Xt|G1|G2]_n @ Wg_n + Bg; sigmoid
// z -> g_Cz (+ fused bf16 split), r -> g_R
// =====================================================================
#define JLDG 193
__global__ __launch_bounds__(256) void gate_mix_kernel() {
    extern __shared__ float sm[];
    float* Ws = sm;
    float* Av = sm + PG;
    const int n = blockIdx.x;
    const int tid = threadIdx.x;

    const float4* wsrc = (const float4*)(g_Wg + (size_t)n * PG);
    float4* wdst = (float4*)Ws;
    for (int i = tid; i < PG/4; i += 256) wdst[i] = wsrc[i];

    const float* s0 = g_Xt + (size_t)n * (BB*DD);
    const float* s1 = g_G1 + (size_t)n * (BB*DD);
    const float* s2 = g_G2 + (size_t)n * (BB*DD);
    for (int t = tid; t < BB*DD; t += 256) {
        int b = t >> 6, i = t & 63;
        Av[b*JLDG +   0 + i] = s0[t];
        Av[b*JLDG +  64 + i] = s1[t];
        Av[b*JLDG + 128 + i] = s2[t];
    }
    __syncthreads();

    const int tx = tid & 31;
    const int ty = tid >> 5;
    float acc[4][4] = {};
#pragma unroll 4
    for (int j = 0; j < KK*DD; j++) {
        float4 wv = *(const float4*)&Ws[j*D2 + tx*4];
        float a0 = Av[(ty*4 + 0)*JLDG + j];
        float a1 = Av[(ty*4 + 1)*JLDG + j];
        float a2 = Av[(ty*4 + 2)*JLDG + j];
        float a3 = Av[(ty*4 + 3)*JLDG + j];
        acc[0][0] = fmaf(a0, wv.x, acc[0][0]); acc[0][1] = fmaf(a0, wv.y, acc[0][1]);
        acc[0][2] = fmaf(a0, wv.z, acc[0][2]); acc[0][3] = fmaf(a0, wv.w, acc[0][3]);
        acc[1][0] = fmaf(a1, wv.x, acc[1][0]); acc[1][1] = fmaf(a1, wv.y, acc[1][1]);
        acc[1][2] = fmaf(a1, wv.z, acc[1][2]); acc[1][3] = fmaf(a1, wv.w, acc[1][3]);
        acc[2][0] = fmaf(a2, wv.x, acc[2][0]); acc[2][1] = fmaf(a2, wv.y, acc[2][1]);
        acc[2][2] = fmaf(a2, wv.z, acc[2][2]); acc[2][3] = fmaf(a2, wv.w, acc[2][3]);
        acc[3][0] = fmaf(a3, wv.x, acc[3][0]); acc[3][1] = fmaf(a3, wv.y, acc[3][1]);
        acc[3][2] = fmaf(a3, wv.z, acc[3][2]); acc[3][3] = fmaf(a3, wv.w, acc[3][3]);
    }
#pragma unroll
    for (int bb = 0; bb < 4; bb++) {
        const int b = ty*4 + bb;
        float4 sv;
        sv.x = 1.f / (1.f + __expf(-(acc[bb][0] + g_Bg[n*D2 + tx*4 + 0])));
        sv.y = 1.f / (1.f + __expf(-(acc[bb][1] + g_Bg[n*D2 + tx*4 + 1])));
        sv.z = 1.f / (1.f + __expf(-(acc[bb][2] + g_Bg[n*D2 + tx*4 + 2])));
        sv.w = 1.f / (1.f + __expf(-(acc[bb][3] + g_Bg[n*D2 + tx*4 + 3])));
        if (tx < 16) {   // z half: o = tx*4 .. +3 in [0,64)
            size_t off = ((size_t)n*BB + b)*DD + tx*4;
            *(float4*)&g_Cz[off] = sv;
            uint2 hi, lo;
            split2(sv.x, sv.y, hi.x, lo.x);
            split2(sv.z, sv.w, hi.y, lo.y);
            *(uint2*)&bCzh[off] = hi;
            *(uint2*)&bCzl[off] = lo;
        } else {         // r half
            *(float4*)&g_R[((size_t)n*BB + b)*DD + (tx - 16)*4] = sv;
        }
    }
}

// =====================================================================
// Update mix: hc = tanh([x|z|G1|H1z|G2|H2z]_n (32x384) @ Wu_n (384x64) + Bu)
// h = r*x + (1-r)*hc -> d_out (B,N,D)
// =====================================================================
#define JLDU 385
__global__ __launch_bounds__(256) void update_mix_kernel(float* __restrict__ out) {
    extern __shared__ float sm[];
    float* Ws = sm;
    float* Av = sm + PU;
    const int n = blockIdx.x;
    const int tid = threadIdx.x;

    const float4* wsrc = (const float4*)(g_Wu + (size_t)n * PU);
    float4* wdst = (float4*)Ws;
    for (int i = tid; i < PU/4; i += 256) wdst[i] = wsrc[i];

    const size_t base = (size_t)n * (BB*DD);
    const float* s0 = g_Xt  + base;
    const float* s1 = g_Cz  + base;
    const float* s2 = g_G1  + base;
    const float* s3 = g_H1z + base;
    const float* s4 = g_G2  + base;
    const float* s5 = g_H2z + base;
    for (int t = tid; t < BB*DD; t += 256) {
        int b = t >> 6, i = t & 63;
        float* av = Av + b*JLDU + i;
        av[  0] = s0[t];
        av[ 64] = s1[t];
        av[128] = s2[t];
        av[192] = s3[t];
        av[256] = s4[t];
        av[320] = s5[t];
    }
    __syncthreads();

    const int tx = tid & 15;
    const int ty = tid >> 4;
    float acc[2][4] = {};
#pragma unroll 4
    for (int j = 0; j < KK*D2; j++) {
        float4 wv = *(const float4*)&Ws[j*DD + tx*4];
        float a0 = Av[(ty*2 + 0)*JLDU + j];
        float a1 = Av[(ty*2 + 1)*JLDU + j];
        acc[0][0] = fmaf(a0, wv.x, acc[0][0]); acc[0][1] = fmaf(a0, wv.y, acc[0][1]);
        acc[0][2] = fmaf(a0, wv.z, acc[0][2]); acc[0][3] = fmaf(a0, wv.w, acc[0][3]);
        acc[1][0] = fmaf(a1, wv.x, acc[1][0]); acc[1][1] = fmaf(a1, wv.y, acc[1][1]);
        acc[1][2] = fmaf(a1, wv.z, acc[1][2]); acc[1][3] = fmaf(a1, wv.w, acc[1][3]);
    }
#pragma unroll
    for (int bb = 0; bb < 2; bb++) {
        int b = ty*2 + bb;
#pragma unroll
        for (int oo = 0; oo < 4; oo++) {
            int o = tx*4 + oo;
            float v  = acc[bb][oo] + g_Bu[n*DD + o];
            float hc = tanhf(v);
            float r  = g_R [((size_t)n*BB + b)*DD + o];
            float xv = g_Xt[((size_t)n*BB + b)*DD + o];
            out[(size_t)b*(NN*DD) + (size_t)n*DD + o] = fmaf(r, xv - hc, hc);
        }
    }
}

// =====================================================================
// Launch
// =====================================================================
extern "C" void kernel_launch(void* const* d_in, const int* in_sizes, int n_in,
                              void* d_out, int out_size) {
    const float* x   = (const float*)d_in[0];
    const float* emb = (const float*)d_in[2];
    const float* gwp = (const float*)d_in[3];
    const float* gbp = (const float*)d_in[4];
    const float* uwp = (const float*)d_in[5];
    const float* ubp = (const float*)d_in[6];
    float* out = (float*)d_out;

    const int GATE_SMEM = (PG + BB*JLDG) * 4;
    const int UPD_SMEM  = (PU + BB*JLDU) * 4;
    cudaFuncSetAttribute(gate_mix_kernel,   cudaFuncAttributeMaxDynamicSharedMemorySize, GATE_SMEM);
    cudaFuncSetAttribute(update_mix_kernel, cudaFuncAttributeMaxDynamicSharedMemorySize, UPD_SMEM);
    cudaFuncSetAttribute(hgemm_kernel,      cudaFuncAttributeMaxDynamicSharedMemorySize, HG_SMEM);

    const dim3 GEMM_GRID(NCOLS/CTN, NN/CTM);   // (16, 16) = 256 CTAs — 1 wave @ occ 2

    adj_kernel<<<NN, 256>>>(emb);                            // adj -> bAh/bAl (fused)
    transpose_kernel<<<(NN*BB*16)/256, 256>>>(x);            // Xt + bXh/bXl (fused)
    wgen_kernel<<<dim3(PG/1024, NN/128), 256>>>(0, emb, gwp);
    wgen_kernel<<<dim3(PU/1024, NN/128), 256>>>(1, emb, uwp);

    hgemm_kernel<<<GEMM_GRID, 256, HG_SMEM>>>(0);            // G1 = A@x (+split)
    hgemm_kernel<<<GEMM_GRID, 256, HG_SMEM>>>(1);            // G2 = 2A@G1 - x

    bgen_gate<<<(NN*D2 + 255)/256, 256>>>(emb, gbp);
    bgen_upd <<<(NN*DD + 255)/256, 256>>>(emb, ubp);

    gate_mix_kernel<<<NN, 256, GATE_SMEM>>>();               // z -> g_Cz (+split), r -> g_R

    hgemm_kernel<<<GEMM_GRID, 256, HG_SMEM>>>(2);            // H1z = A@z (+split)
    hgemm_kernel<<<GEMM_GRID, 256, HG_SMEM>>>(3);            // H2z = 2A@H1z - z

    update_mix_kernel<<<NN, 256, UPD_SMEM>>>(out);
}